// round 8
// baseline (speedup 1.0000x reference)
#include <cuda_runtime.h>
#include <math.h>
#include <stdint.h>

#define BB  2
#define TT  2048
#define DD  1024
#define HH  16
#define DKK 64
#define BH  (BB*HH)

// Scratch (allocation-free): q,k,v in [B*H, T, 64]; o in [B, T, D] (heads concatenated)
__device__ float g_q[(size_t)BH * TT * DKK];
__device__ float g_k[(size_t)BH * TT * DKK];
__device__ float g_v[(size_t)BH * TT * DKK];
__device__ float g_o[(size_t)BB * TT * DD];

__device__ __forceinline__ float fast_exp2(float x) {
    float y;
    asm("ex2.approx.ftz.f32 %0, %1;" : "=f"(y) : "f"(x));
    return y;
}

__device__ __forceinline__ uint32_t f2tf32(float x) {
    uint32_t r;
    asm("cvt.rna.tf32.f32 %0, %1;" : "=r"(r) : "f"(x));
    return r;
}

// D(16x8,f32) += A(16x8,tf32) * B(8x8,tf32)   row.col
__device__ __forceinline__ void mma_tf32(
    float& c0, float& c1, float& c2, float& c3,
    uint32_t a0, uint32_t a1, uint32_t a2, uint32_t a3,
    uint32_t b0, uint32_t b1)
{
    asm volatile(
        "mma.sync.aligned.m16n8k8.row.col.f32.tf32.tf32.f32 "
        "{%0,%1,%2,%3}, {%4,%5,%6,%7}, {%8,%9}, {%0,%1,%2,%3};"
        : "+f"(c0), "+f"(c1), "+f"(c2), "+f"(c3)
        : "r"(a0), "r"(a1), "r"(a2), "r"(a3), "r"(b0), "r"(b1));
}

// ---------------------------------------------------------------------------
// Kernel 1: per-head QKV projection, TF32 tensor cores.
// grid = (T/128, B*H), 256 threads = 8 warps. Tile: 128 tokens x (3x64) out.
// ---------------------------------------------------------------------------
__global__ __launch_bounds__(256) void qkv_kernel(
    const float* __restrict__ x,  const float* __restrict__ Wq,
    const float* __restrict__ Wk, const float* __restrict__ Wv)
{
    extern __shared__ float sm[];
    uint32_t* Xu  = (uint32_t*)sm;        // [128][68]
    uint32_t* Wqu = Xu  + 128 * 68;       // [64][68]
    uint32_t* Wku = Wqu + 64 * 68;
    uint32_t* Wvu = Wku + 64 * 68;

    const int bh = blockIdx.y;
    const int b  = bh >> 4, h = bh & 15;
    const int t0 = blockIdx.x * 128;
    const int tid = threadIdx.x;
    const int wid = tid >> 5, lane = tid & 31;
    const int g = lane >> 2, tig = lane & 3;
    const int wrow = wid * 16;

    {
        const int c4 = tid & 15, r0 = tid >> 4;
        const float* xp = x + ((size_t)(b * TT + t0)) * DD + h * DKK;
        #pragma unroll
        for (int r = 0; r < 8; r++) {
            const int row = r0 + r * 16;
            float4 v = *(const float4*)(xp + (size_t)row * DD + c4 * 4);
            uint4 u = { f2tf32(v.x), f2tf32(v.y), f2tf32(v.z), f2tf32(v.w) };
            *(uint4*)&Xu[row * 68 + c4 * 4] = u;
        }
        const float* wqp = Wq + (size_t)h * DKK * DKK;
        const float* wkp = Wk + (size_t)h * DKK * DKK;
        const float* wvp = Wv + (size_t)h * DKK * DKK;
        #pragma unroll
        for (int r = 0; r < 4; r++) {
            const int row = r0 + r * 16;
            float4 vq = *(const float4*)(wqp + row * 64 + c4 * 4);
            float4 vk = *(const float4*)(wkp + row * 64 + c4 * 4);
            float4 vv = *(const float4*)(wvp + row * 64 + c4 * 4);
            uint4 uq = { f2tf32(vq.x), f2tf32(vq.y), f2tf32(vq.z), f2tf32(vq.w) };
            uint4 uk = { f2tf32(vk.x), f2tf32(vk.y), f2tf32(vk.z), f2tf32(vk.w) };
            uint4 uv = { f2tf32(vv.x), f2tf32(vv.y), f2tf32(vv.z), f2tf32(vv.w) };
            *(uint4*)&Wqu[row * 68 + c4 * 4] = uq;
            *(uint4*)&Wku[row * 68 + c4 * 4] = uk;
            *(uint4*)&Wvu[row * 68 + c4 * 4] = uv;
        }
    }
    __syncthreads();

    float aq[8][4], ak[8][4], av[8][4];
    #pragma unroll
    for (int nb = 0; nb < 8; nb++)
        #pragma unroll
        for (int c = 0; c < 4; c++) { aq[nb][c]=0.f; ak[nb][c]=0.f; av[nb][c]=0.f; }

    const int ar0 = (wrow + g) * 68;
    const int ar1 = (wrow + g + 8) * 68;

    #pragma unroll
    for (int k0 = 0; k0 < 64; k0 += 8) {
        const uint32_t a0 = Xu[ar0 + k0 + tig];
        const uint32_t a1 = Xu[ar1 + k0 + tig];
        const uint32_t a2 = Xu[ar0 + k0 + tig + 4];
        const uint32_t a3 = Xu[ar1 + k0 + tig + 4];
        #pragma unroll
        for (int nb = 0; nb < 8; nb++) {
            const int br = (nb * 8 + g) * 68 + k0 + tig;
            mma_tf32(aq[nb][0], aq[nb][1], aq[nb][2], aq[nb][3],
                     a0, a1, a2, a3, Wqu[br], Wqu[br + 4]);
            mma_tf32(ak[nb][0], ak[nb][1], ak[nb][2], ak[nb][3],
                     a0, a1, a2, a3, Wku[br], Wku[br + 4]);
            mma_tf32(av[nb][0], av[nb][1], av[nb][2], av[nb][3],
                     a0, a1, a2, a3, Wvu[br], Wvu[br + 4]);
        }
    }

    #pragma unroll
    for (int rs = 0; rs < 2; rs++) {
        const size_t row = (size_t)bh * TT + t0 + wrow + g + 8 * rs;
        float* qo = g_q + row * DKK;
        float* ko = g_k + row * DKK;
        float* vo = g_v + row * DKK;
        #pragma unroll
        for (int nb = 0; nb < 8; nb++) {
            const int c = nb * 8 + 2 * tig;
            float2 vq2 = { aq[nb][2*rs], aq[nb][2*rs+1] };
            float2 vk2 = { ak[nb][2*rs], ak[nb][2*rs+1] };
            float2 vv2 = { av[nb][2*rs], av[nb][2*rs+1] };
            *(float2*)(qo + c) = vq2;
            *(float2*)(ko + c) = vk2;
            *(float2*)(vo + c) = vv2;
        }
    }
}

// ---------------------------------------------------------------------------
// Kernel 2: causal flash attention, TF32, single-buffer K/V + register
// double-buffering, 2 CTAs/SM. grid = (T/128, B*H), 256 threads = 8 warps.
// Dynamic smem: (128*68 + 64*68 + 64*72 + 128*68)*4 = 105,472 B  (2/SM)
// ---------------------------------------------------------------------------
__global__ __launch_bounds__(256, 2) void attn_kernel()
{
    extern __shared__ float sm[];
    uint32_t* Qu = (uint32_t*)sm;             // [128][68]
    uint32_t* Ku = Qu + 128 * 68;             // [64][68]
    uint32_t* Vu = Ku + 64 * 68;              // [64][72]
    uint32_t* Pu = Vu + 64 * 72;              // [128][68]

    const int bh  = blockIdx.y;
    const int q0  = (gridDim.x - 1 - blockIdx.x) * 128;  // heavy blocks first
    const int tid = threadIdx.x;
    const int wid = tid >> 5, lane = tid & 31;
    const int g   = lane >> 2, tig = lane & 3;
    const int wrow = wid * 16;
    const int ar0  = (wrow + g) * 68;
    const int ar1  = (wrow + g + 8) * 68;
    const int c4 = tid & 15, sr0 = tid >> 4;

    const float* Qg = g_q + ((size_t)bh * TT + q0) * DKK;
    const float* Kg = g_k + (size_t)bh * TT * DKK;
    const float* Vg = g_v + (size_t)bh * TT * DKK;

    // stage Q tile
    #pragma unroll
    for (int r = 0; r < 8; r++) {
        const int row = sr0 + r * 16;
        float4 v = *(const float4*)(Qg + (size_t)row * DKK + c4 * 4);
        uint4 u = { f2tf32(v.x), f2tf32(v.y), f2tf32(v.z), f2tf32(v.w) };
        *(uint4*)&Qu[row * 68 + c4 * 4] = u;
    }
    // stage K/V tile 0
    #pragma unroll
    for (int r = 0; r < 4; r++) {
        const int row = sr0 + r * 16;
        float4 vk = *(const float4*)(Kg + (size_t)row * DKK + c4 * 4);
        float4 vv = *(const float4*)(Vg + (size_t)row * DKK + c4 * 4);
        uint4 uk = { f2tf32(vk.x), f2tf32(vk.y), f2tf32(vk.z), f2tf32(vk.w) };
        uint4 uv = { f2tf32(vv.x), f2tf32(vv.y), f2tf32(vv.z), f2tf32(vv.w) };
        *(uint4*)&Ku[row * 68 + c4 * 4] = uk;
        *(uint4*)&Vu[row * 72 + c4 * 4] = uv;
    }

    float o[8][4];
    #pragma unroll
    for (int nb = 0; nb < 8; nb++)
        #pragma unroll
        for (int c = 0; c < 4; c++) o[nb][c] = 0.f;
    float mrow[2] = { -1e30f, -1e30f };
    float lrow[2] = { 0.f, 0.f };

    const float l2s = 0.18033688011112042f;  // (1/sqrt(64)) * log2(e)
    const int ntiles = q0 / 64 + 2;
    const int rowmax = q0 + wrow + 15;       // this warp's max Q row index

    __syncthreads();

    for (int kt = 0; kt < ntiles; kt++) {
        const int k0t = kt * 64;
        const int knext = min((kt + 1) * 64, TT - 64);
        const bool active = (k0t <= rowmax);   // skip fully-masked warp-tiles

        // prefetch next K tile into registers
        float4 rk[4];
        #pragma unroll
        for (int r = 0; r < 4; r++)
            rk[r] = *(const float4*)(Kg + (size_t)(knext + sr0 + r * 16) * DKK + c4 * 4);

        float4 rv[4];

        if (active) {
            // S = Q K^T : warp 16x64
            float sA[8][4];
            #pragma unroll
            for (int nb = 0; nb < 8; nb++)
                #pragma unroll
                for (int c = 0; c < 4; c++) sA[nb][c] = 0.f;

            #pragma unroll
            for (int k0 = 0; k0 < 64; k0 += 8) {
                const uint32_t a0 = Qu[ar0 + k0 + tig];
                const uint32_t a1 = Qu[ar1 + k0 + tig];
                const uint32_t a2 = Qu[ar0 + k0 + tig + 4];
                const uint32_t a3 = Qu[ar1 + k0 + tig + 4];
                #pragma unroll
                for (int nb = 0; nb < 8; nb++) {
                    const int br = (nb * 8 + g) * 68 + k0 + tig;
                    mma_tf32(sA[nb][0], sA[nb][1], sA[nb][2], sA[nb][3],
                             a0, a1, a2, a3, Ku[br], Ku[br + 4]);
                }
            }

            // per-row-slot online softmax (rows warp-private)
            #pragma unroll
            for (int rs = 0; rs < 2; rs++) {
                const int qrow = q0 + wrow + g + 8 * rs;
                if (k0t + 63 > qrow) {
                    #pragma unroll
                    for (int nb = 0; nb < 8; nb++) {
                        const int c0 = k0t + nb * 8 + 2 * tig;
                        if (c0     > qrow) sA[nb][2*rs]     = -1e30f;
                        if (c0 + 1 > qrow) sA[nb][2*rs + 1] = -1e30f;
                    }
                }
                float rm = -1e30f;
                #pragma unroll
                for (int nb = 0; nb < 8; nb++)
                    rm = fmaxf(rm, fmaxf(sA[nb][2*rs], sA[nb][2*rs+1]));
                rm = fmaxf(rm, __shfl_xor_sync(0xffffffffu, rm, 1));
                rm = fmaxf(rm, __shfl_xor_sync(0xffffffffu, rm, 2));
                const float mn = fmaxf(mrow[rs], rm);
                const float alpha = fast_exp2((mrow[rs] - mn) * l2s);
                mrow[rs] = mn;
                float rsum = 0.f;
                #pragma unroll
                for (int nb = 0; nb < 8; nb++) {
                    float p0 = fast_exp2((sA[nb][2*rs]   - mn) * l2s);
                    float p1 = fast_exp2((sA[nb][2*rs+1] - mn) * l2s);
                    sA[nb][2*rs] = p0; sA[nb][2*rs+1] = p1;
                    rsum += p0 + p1;
                }
                rsum += __shfl_xor_sync(0xffffffffu, rsum, 1);
                rsum += __shfl_xor_sync(0xffffffffu, rsum, 2);
                lrow[rs] = lrow[rs] * alpha + rsum;
                #pragma unroll
                for (int nb = 0; nb < 8; nb++) {
                    o[nb][2*rs]   *= alpha;
                    o[nb][2*rs+1] *= alpha;
                }
                const int prow = (wrow + g + 8 * rs) * 68;
                #pragma unroll
                for (int nb = 0; nb < 8; nb++) {
                    uint2 pv = { f2tf32(sA[nb][2*rs]), f2tf32(sA[nb][2*rs+1]) };
                    *(uint2*)&Pu[prow + nb * 8 + 2 * tig] = pv;
                }
            }
            __syncwarp();
        }

        // prefetch next V tile into registers (S regs now dead)
        #pragma unroll
        for (int r = 0; r < 4; r++)
            rv[r] = *(const float4*)(Vg + (size_t)(knext + sr0 + r * 16) * DKK + c4 * 4);

        if (active) {
            // O += P V
            #pragma unroll
            for (int k0 = 0; k0 < 64; k0 += 8) {
                const uint32_t a0 = Pu[ar0 + k0 + tig];
                const uint32_t a1 = Pu[ar1 + k0 + tig];
                const uint32_t a2 = Pu[ar0 + k0 + tig + 4];
                const uint32_t a3 = Pu[ar1 + k0 + tig + 4];
                const int vb0 = (k0 + tig) * 72 + g;
                const int vb1 = (k0 + tig + 4) * 72 + g;
                #pragma unroll
                for (int nb = 0; nb < 8; nb++) {
                    mma_tf32(o[nb][0], o[nb][1], o[nb][2], o[nb][3],
                             a0, a1, a2, a3, Vu[vb0 + nb * 8], Vu[vb1 + nb * 8]);
                }
            }
        }

        __syncthreads();   // everyone done reading Ku/Vu
        // STS prefetched tile into the (single) buffer
        #pragma unroll
        for (int r = 0; r < 4; r++) {
            const int row = sr0 + r * 16;
            uint4 uk = { f2tf32(rk[r].x), f2tf32(rk[r].y), f2tf32(rk[r].z), f2tf32(rk[r].w) };
            uint4 uv = { f2tf32(rv[r].x), f2tf32(rv[r].y), f2tf32(rv[r].z), f2tf32(rv[r].w) };
            *(uint4*)&Ku[row * 68 + c4 * 4] = uk;
            *(uint4*)&Vu[row * 72 + c4 * 4] = uv;
        }
        __syncthreads();   // staged for next iteration
    }

    // normalize and store concat-heads layout
    const int b = bh >> 4, h = bh & 15;
    float* Og = g_o + ((size_t)(b * TT + q0)) * DD + h * DKK;
    #pragma unroll
    for (int rs = 0; rs < 2; rs++) {
        const float inv = 1.0f / lrow[rs];
        float* orow = Og + (size_t)(wrow + g + 8 * rs) * DD;
        #pragma unroll
        for (int nb = 0; nb < 8; nb++) {
            float2 v = { o[nb][2*rs] * inv, o[nb][2*rs+1] * inv };
            *(float2*)(orow + nb * 8 + 2 * tig) = v;
        }
    }
}

// ---------------------------------------------------------------------------
// Kernel 3: output projection y = o @ Wp^T + bp, TF32, double-buffered BK=32.
// grid = (D/128, B*T/128), 256 threads = 8 warps (4M x 2N), warp 32x64.
// Dynamic smem: 4 * 128*36 * 4 = 73,728 B
// ---------------------------------------------------------------------------
__global__ __launch_bounds__(256) void proj_kernel(
    const float* __restrict__ Wp, const float* __restrict__ bp,
    float* __restrict__ y)
{
    extern __shared__ float psm[];
    uint32_t* Ob = (uint32_t*)psm;          // [2][128*36]
    uint32_t* Wb = Ob + 2 * 128 * 36;       // [2][128*36]

    const int j0 = blockIdx.x * 128;
    const int r0 = blockIdx.y * 128;
    const int tid = threadIdx.x;
    const int wid = tid >> 5, lane = tid & 31;
    const int g = lane >> 2, tig = lane & 3;
    const int wm = wid & 3, wn = wid >> 2;
    const int c4 = tid & 7, rb = tid >> 3;

    #pragma unroll
    for (int r = 0; r < 4; r++) {
        const int row = rb + 32 * r;
        float4 vo = *(const float4*)(g_o + (size_t)(r0 + row) * DD + c4 * 4);
        float4 vw = *(const float4*)(Wp  + (size_t)(j0 + row) * DD + c4 * 4);
        uint4 uo = { f2tf32(vo.x), f2tf32(vo.y), f2tf32(vo.z), f2tf32(vo.w) };
        uint4 uw = { f2tf32(vw.x), f2tf32(vw.y), f2tf32(vw.z), f2tf32(vw.w) };
        *(uint4*)&Ob[row * 36 + c4 * 4] = uo;
        *(uint4*)&Wb[row * 36 + c4 * 4] = uw;
    }

    float acc[2][8][4];
    #pragma unroll
    for (int mf = 0; mf < 2; mf++)
        #pragma unroll
        for (int nb = 0; nb < 8; nb++)
            #pragma unroll
            for (int c = 0; c < 4; c++) acc[mf][nb][c] = 0.f;

    for (int it = 0; it < 32; it++) {
        const int kcn = min((it + 1) * 32, DD - 32);
        float4 ro[4], rw[4];
        #pragma unroll
        for (int r = 0; r < 4; r++) {
            const int row = rb + 32 * r;
            ro[r] = *(const float4*)(g_o + (size_t)(r0 + row) * DD + kcn + c4 * 4);
            rw[r] = *(const float4*)(Wp  + (size_t)(j0 + row) * DD + kcn + c4 * 4);
        }
        __syncthreads();
        const uint32_t* Ou = Ob + (it & 1) * 128 * 36;
        const uint32_t* Wu = Wb + (it & 1) * 128 * 36;

        #pragma unroll
        for (int k8 = 0; k8 < 4; k8++) {
            const int kk = k8 * 8;
            uint32_t a[2][4];
            #pragma unroll
            for (int mf = 0; mf < 2; mf++) {
                const int ar = (wm * 32 + mf * 16 + g) * 36 + kk + tig;
                a[mf][0] = Ou[ar];
                a[mf][1] = Ou[ar + 8 * 36];
                a[mf][2] = Ou[ar + 4];
                a[mf][3] = Ou[ar + 8 * 36 + 4];
            }
            #pragma unroll
            for (int nb = 0; nb < 8; nb++) {
                const int br = (wn * 64 + nb * 8 + g) * 36 + kk + tig;
                const uint32_t b0 = Wu[br], b1 = Wu[br + 4];
                mma_tf32(acc[0][nb][0], acc[0][nb][1], acc[0][nb][2], acc[0][nb][3],
                         a[0][0], a[0][1], a[0][2], a[0][3], b0, b1);
                mma_tf32(acc[1][nb][0], acc[1][nb][1], acc[1][nb][2], acc[1][nb][3],
                         a[1][0], a[1][1], a[1][2], a[1][3], b0, b1);
            }
        }

        {
            uint32_t* Ow = Ob + ((it + 1) & 1) * 128 * 36;
            uint32_t* Ww = Wb + ((it + 1) & 1) * 128 * 36;
            #pragma unroll
            for (int r = 0; r < 4; r++) {
                const int row = rb + 32 * r;
                uint4 uo = { f2tf32(ro[r].x), f2tf32(ro[r].y), f2tf32(ro[r].z), f2tf32(ro[r].w) };
                uint4 uw = { f2tf32(rw[r].x), f2tf32(rw[r].y), f2tf32(rw[r].z), f2tf32(rw[r].w) };
                *(uint4*)&Ow[row * 36 + c4 * 4] = uo;
                *(uint4*)&Ww[row * 36 + c4 * 4] = uw;
            }
        }
    }

    #pragma unroll
    for (int mf = 0; mf < 2; mf++)
        #pragma unroll
        for (int rs = 0; rs < 2; rs++) {
            const int row = r0 + wm * 32 + mf * 16 + g + 8 * rs;
            float* yr = y + (size_t)row * DD + j0 + wn * 64;
            const float* br = bp + j0 + wn * 64;
            #pragma unroll
            for (int nb = 0; nb < 8; nb++) {
                const int c = nb * 8 + 2 * tig;
                float2 v = { acc[mf][nb][2*rs]   + br[c],
                             acc[mf][nb][2*rs+1] + br[c + 1] };
                *(float2*)(yr + c) = v;
            }
        }
}

// ---------------------------------------------------------------------------
#define QKV_SMEM  ((128*68 + 3*64*68) * (int)sizeof(float))                    // 87,040
#define ATTN_SMEM ((128*68 + 64*68 + 64*72 + 128*68) * (int)sizeof(float))     // 105,472
#define PROJ_SMEM (4 * 128 * 36 * (int)sizeof(float))                          // 73,728

extern "C" void kernel_launch(void* const* d_in, const int* in_sizes, int n_in,
                              void* d_out, int out_size)
{
    const float* x  = (const float*)d_in[0];
    const float* Wq = (const float*)d_in[1];
    const float* Wk = (const float*)d_in[2];
    const float* Wv = (const float*)d_in[3];
    const float* Wp = (const float*)d_in[4];
    const float* bp = (const float*)d_in[5];
    float* y = (float*)d_out;

    cudaFuncSetAttribute(qkv_kernel,  cudaFuncAttributeMaxDynamicSharedMemorySize, QKV_SMEM);
    cudaFuncSetAttribute(attn_kernel, cudaFuncAttributeMaxDynamicSharedMemorySize, ATTN_SMEM);
    cudaFuncSetAttribute(proj_kernel, cudaFuncAttributeMaxDynamicSharedMemorySize, PROJ_SMEM);

    qkv_kernel<<<dim3(TT / 128, BH), 256, QKV_SMEM>>>(x, Wq, Wk, Wv);
    attn_kernel<<<dim3(TT / 128, BH), 256, ATTN_SMEM>>>();
    proj_kernel<<<dim3(DD / 128, (BB * TT) / 128), 256, PROJ_SMEM>>>(Wp, bp, y);
}

// round 10
// speedup vs baseline: 1.0127x; 1.0127x over previous
#include <cuda_runtime.h>
#include <math.h>
#include <stdint.h>

#define BB  2
#define TT  2048
#define DD  1024
#define HH  16
#define DKK 64
#define BH  (BB*HH)

// Scratch (allocation-free): q,k,v in [B*H, T, 64]; o in [B, T, D] (heads concatenated)
__device__ float g_q[(size_t)BH * TT * DKK];
__device__ float g_k[(size_t)BH * TT * DKK];
__device__ float g_v[(size_t)BH * TT * DKK];
__device__ float g_o[(size_t)BB * TT * DD];

__device__ __forceinline__ float fast_exp2(float x) {
    float y;
    asm("ex2.approx.ftz.f32 %0, %1;" : "=f"(y) : "f"(x));
    return y;
}

__device__ __forceinline__ uint32_t f2tf32(float x) {
    uint32_t r;
    asm("cvt.rna.tf32.f32 %0, %1;" : "=r"(r) : "f"(x));
    return r;
}

// D(16x8,f32) += A(16x8,tf32) * B(8x8,tf32)   row.col
__device__ __forceinline__ void mma_tf32(
    float& c0, float& c1, float& c2, float& c3,
    uint32_t a0, uint32_t a1, uint32_t a2, uint32_t a3,
    uint32_t b0, uint32_t b1)
{
    asm volatile(
        "mma.sync.aligned.m16n8k8.row.col.f32.tf32.tf32.f32 "
        "{%0,%1,%2,%3}, {%4,%5,%6,%7}, {%8,%9}, {%0,%1,%2,%3};"
        : "+f"(c0), "+f"(c1), "+f"(c2), "+f"(c3)
        : "r"(a0), "r"(a1), "r"(a2), "r"(a3), "r"(b0), "r"(b1));
}

// ---------------------------------------------------------------------------
// Kernel 1: per-head QKV projection, TF32 tensor cores. (unchanged, 22.9us)
// ---------------------------------------------------------------------------
__global__ __launch_bounds__(256) void qkv_kernel(
    const float* __restrict__ x,  const float* __restrict__ Wq,
    const float* __restrict__ Wk, const float* __restrict__ Wv)
{
    extern __shared__ float sm[];
    uint32_t* Xu  = (uint32_t*)sm;        // [128][68]
    uint32_t* Wqu = Xu  + 128 * 68;       // [64][68]
    uint32_t* Wku = Wqu + 64 * 68;
    uint32_t* Wvu = Wku + 64 * 68;

    const int bh = blockIdx.y;
    const int b  = bh >> 4, h = bh & 15;
    const int t0 = blockIdx.x * 128;
    const int tid = threadIdx.x;
    const int wid = tid >> 5, lane = tid & 31;
    const int g = lane >> 2, tig = lane & 3;
    const int wrow = wid * 16;

    {
        const int c4 = tid & 15, r0 = tid >> 4;
        const float* xp = x + ((size_t)(b * TT + t0)) * DD + h * DKK;
        #pragma unroll
        for (int r = 0; r < 8; r++) {
            const int row = r0 + r * 16;
            float4 v = *(const float4*)(xp + (size_t)row * DD + c4 * 4);
            uint4 u = { f2tf32(v.x), f2tf32(v.y), f2tf32(v.z), f2tf32(v.w) };
            *(uint4*)&Xu[row * 68 + c4 * 4] = u;
        }
        const float* wqp = Wq + (size_t)h * DKK * DKK;
        const float* wkp = Wk + (size_t)h * DKK * DKK;
        const float* wvp = Wv + (size_t)h * DKK * DKK;
        #pragma unroll
        for (int r = 0; r < 4; r++) {
            const int row = r0 + r * 16;
            float4 vq = *(const float4*)(wqp + row * 64 + c4 * 4);
            float4 vk = *(const float4*)(wkp + row * 64 + c4 * 4);
            float4 vv = *(const float4*)(wvp + row * 64 + c4 * 4);
            uint4 uq = { f2tf32(vq.x), f2tf32(vq.y), f2tf32(vq.z), f2tf32(vq.w) };
            uint4 uk = { f2tf32(vk.x), f2tf32(vk.y), f2tf32(vk.z), f2tf32(vk.w) };
            uint4 uv = { f2tf32(vv.x), f2tf32(vv.y), f2tf32(vv.z), f2tf32(vv.w) };
            *(uint4*)&Wqu[row * 68 + c4 * 4] = uq;
            *(uint4*)&Wku[row * 68 + c4 * 4] = uk;
            *(uint4*)&Wvu[row * 68 + c4 * 4] = uv;
        }
    }
    __syncthreads();

    float aq[8][4], ak[8][4], av[8][4];
    #pragma unroll
    for (int nb = 0; nb < 8; nb++)
        #pragma unroll
        for (int c = 0; c < 4; c++) { aq[nb][c]=0.f; ak[nb][c]=0.f; av[nb][c]=0.f; }

    const int ar0 = (wrow + g) * 68;
    const int ar1 = (wrow + g + 8) * 68;

    #pragma unroll
    for (int k0 = 0; k0 < 64; k0 += 8) {
        const uint32_t a0 = Xu[ar0 + k0 + tig];
        const uint32_t a1 = Xu[ar1 + k0 + tig];
        const uint32_t a2 = Xu[ar0 + k0 + tig + 4];
        const uint32_t a3 = Xu[ar1 + k0 + tig + 4];
        #pragma unroll
        for (int nb = 0; nb < 8; nb++) {
            const int br = (nb * 8 + g) * 68 + k0 + tig;
            mma_tf32(aq[nb][0], aq[nb][1], aq[nb][2], aq[nb][3],
                     a0, a1, a2, a3, Wqu[br], Wqu[br + 4]);
            mma_tf32(ak[nb][0], ak[nb][1], ak[nb][2], ak[nb][3],
                     a0, a1, a2, a3, Wku[br], Wku[br + 4]);
            mma_tf32(av[nb][0], av[nb][1], av[nb][2], av[nb][3],
                     a0, a1, a2, a3, Wvu[br], Wvu[br + 4]);
        }
    }

    #pragma unroll
    for (int rs = 0; rs < 2; rs++) {
        const size_t row = (size_t)bh * TT + t0 + wrow + g + 8 * rs;
        float* qo = g_q + row * DKK;
        float* ko = g_k + row * DKK;
        float* vo = g_v + row * DKK;
        #pragma unroll
        for (int nb = 0; nb < 8; nb++) {
            const int c = nb * 8 + 2 * tig;
            float2 vq2 = { aq[nb][2*rs], aq[nb][2*rs+1] };
            float2 vk2 = { ak[nb][2*rs], ak[nb][2*rs+1] };
            float2 vv2 = { av[nb][2*rs], av[nb][2*rs+1] };
            *(float2*)(qo + c) = vq2;
            *(float2*)(ko + c) = vk2;
            *(float2*)(vo + c) = vv2;
        }
    }
}

// ---------------------------------------------------------------------------
// Kernel 2: causal flash attention, TF32, double-buffered K/V (R5 staging),
// 4x2 warp grid: each warp 32 Q-rows x 32 K-cols. Pair-wise softmax via
// named barrier; O kept column-split per warp, pair-reduced at the end.
// Dynamic smem: (128*68 + 2*64*68 + 2*64*72 + 128*68)*4 + 2*128*8 = 143,360 B
// ---------------------------------------------------------------------------
__global__ __launch_bounds__(256, 1) void attn_kernel()
{
    extern __shared__ float sm[];
    uint32_t* Qu = (uint32_t*)sm;             // [128][68]
    uint32_t* Kb = Qu + 128 * 68;             // [2][64][68]
    uint32_t* Vb = Kb + 2 * 64 * 68;          // [2][64][72]
    uint32_t* Pu = Vb + 2 * 64 * 72;          // [128][68] (P tile; reused for O reduce)
    float2*   ML = (float2*)(Pu + 128 * 68);  // [2][128] pair exchange (m, l)
    float*    Pf = (float*)Pu;

    const int bh  = blockIdx.y;
    const int q0  = (gridDim.x - 1 - blockIdx.x) * 128;  // heavy blocks first
    const int tid = threadIdx.x;
    const int wid = tid >> 5, lane = tid & 31;
    const int g   = lane >> 2, tig = lane & 3;
    const int wm  = wid & 3, wn = wid >> 2;
    const int rb  = wm * 32;                  // warp's Q-row base in tile
    const int cb  = wn * 32;                  // warp's K-col base in tile
    const int c4 = tid & 15, sr0 = tid >> 4;

    const float* Qg = g_q + ((size_t)bh * TT + q0) * DKK;
    const float* Kg = g_k + (size_t)bh * TT * DKK;
    const float* Vg = g_v + (size_t)bh * TT * DKK;

    // stage Q tile
    #pragma unroll
    for (int r = 0; r < 8; r++) {
        const int row = sr0 + r * 16;
        float4 v = *(const float4*)(Qg + (size_t)row * DKK + c4 * 4);
        uint4 u = { f2tf32(v.x), f2tf32(v.y), f2tf32(v.z), f2tf32(v.w) };
        *(uint4*)&Qu[row * 68 + c4 * 4] = u;
    }
    // stage K/V tile 0 into buffer 0
    #pragma unroll
    for (int r = 0; r < 4; r++) {
        const int row = sr0 + r * 16;
        float4 vk = *(const float4*)(Kg + (size_t)row * DKK + c4 * 4);
        float4 vv = *(const float4*)(Vg + (size_t)row * DKK + c4 * 4);
        uint4 uk = { f2tf32(vk.x), f2tf32(vk.y), f2tf32(vk.z), f2tf32(vk.w) };
        uint4 uv = { f2tf32(vv.x), f2tf32(vv.y), f2tf32(vv.z), f2tf32(vv.w) };
        *(uint4*)&Kb[row * 68 + c4 * 4] = uk;
        *(uint4*)&Vb[row * 72 + c4 * 4] = uv;
    }

    // O partial (over this warp's 32 K-cols): rows 32 x d 64 -> [2 mf][8 nb][4]
    float acc[2][8][4];
    #pragma unroll
    for (int mf = 0; mf < 2; mf++)
        #pragma unroll
        for (int nb = 0; nb < 8; nb++)
            #pragma unroll
            for (int c = 0; c < 4; c++) acc[mf][nb][c] = 0.f;
    // running state per row-slot: rs = mf*2 + s, row = rb + mf*16 + g + 8*s
    float mr[4] = { -1e30f, -1e30f, -1e30f, -1e30f };
    float lr[4] = { 0.f, 0.f, 0.f, 0.f };

    const float l2s = 0.18033688011112042f;  // (1/sqrt(64)) * log2(e)
    const int ntiles = q0 / 64 + 2;
    const int rowmax = q0 + rb + 31;

    for (int kt = 0; kt < ntiles; kt++) {
        const int k0t = kt * 64;
        const int knext = min((kt + 1) * 64, TT - 64);
        const bool active = (k0t <= rowmax);

        // prefetch next K tile into registers
        float4 rk[4];
        #pragma unroll
        for (int r = 0; r < 4; r++)
            rk[r] = *(const float4*)(Kg + (size_t)(knext + sr0 + r * 16) * DKK + c4 * 4);

        __syncthreads();   // current buffer staged; prior reads of it long done
        const uint32_t* Ku = Kb + (kt & 1) * 64 * 68;
        const uint32_t* Vu = Vb + (kt & 1) * 64 * 72;

        float4 rv[4];

        if (active) {
            // ---- S = Q K^T : warp 32x32, 8 k-steps of m16n8k8, 2 mf x 4 nb
            float sA[2][4][4];
            #pragma unroll
            for (int mf = 0; mf < 2; mf++)
                #pragma unroll
                for (int nb = 0; nb < 4; nb++)
                    #pragma unroll
                    for (int c = 0; c < 4; c++) sA[mf][nb][c] = 0.f;

            #pragma unroll
            for (int k0 = 0; k0 < 64; k0 += 8) {
                uint32_t a[2][4];
                #pragma unroll
                for (int mf = 0; mf < 2; mf++) {
                    const int ar = (rb + mf * 16 + g) * 68 + k0 + tig;
                    a[mf][0] = Qu[ar];
                    a[mf][1] = Qu[ar + 8 * 68];
                    a[mf][2] = Qu[ar + 4];
                    a[mf][3] = Qu[ar + 8 * 68 + 4];
                }
                #pragma unroll
                for (int nb = 0; nb < 4; nb++) {
                    const int br = (cb + nb * 8 + g) * 68 + k0 + tig;
                    const uint32_t b0 = Ku[br], b1 = Ku[br + 4];
                    mma_tf32(sA[0][nb][0], sA[0][nb][1], sA[0][nb][2], sA[0][nb][3],
                             a[0][0], a[0][1], a[0][2], a[0][3], b0, b1);
                    mma_tf32(sA[1][nb][0], sA[1][nb][1], sA[1][nb][2], sA[1][nb][3],
                             a[1][0], a[1][1], a[1][2], a[1][3], b0, b1);
                }
            }

            // ---- causal mask (only when this warp's col range can exceed rows)
            if (k0t + cb + 31 > q0 + rb) {
                #pragma unroll
                for (int mf = 0; mf < 2; mf++)
                    #pragma unroll
                    for (int s = 0; s < 2; s++) {
                        const int qrow = q0 + rb + mf * 16 + g + 8 * s;
                        #pragma unroll
                        for (int nb = 0; nb < 4; nb++) {
                            const int c0 = k0t + cb + nb * 8 + 2 * tig;
                            if (c0     > qrow) sA[mf][nb][2*s]   = -1e30f;
                            if (c0 + 1 > qrow) sA[mf][nb][2*s+1] = -1e30f;
                        }
                    }
            }

            // ---- warp-partial softmax stats; write (m,l) for pair exchange
            float m_p[4], l_p[4];
            #pragma unroll
            for (int mf = 0; mf < 2; mf++)
                #pragma unroll
                for (int s = 0; s < 2; s++) {
                    const int rs = mf * 2 + s;
                    float rm = -1e30f;
                    #pragma unroll
                    for (int nb = 0; nb < 4; nb++)
                        rm = fmaxf(rm, fmaxf(sA[mf][nb][2*s], sA[mf][nb][2*s+1]));
                    rm = fmaxf(rm, __shfl_xor_sync(0xffffffffu, rm, 1));
                    rm = fmaxf(rm, __shfl_xor_sync(0xffffffffu, rm, 2));
                    m_p[rs] = rm;
                    float ls = 0.f;
                    #pragma unroll
                    for (int nb = 0; nb < 4; nb++) {
                        float p0 = fast_exp2((sA[mf][nb][2*s]   - rm) * l2s);
                        float p1 = fast_exp2((sA[mf][nb][2*s+1] - rm) * l2s);
                        sA[mf][nb][2*s] = p0; sA[mf][nb][2*s+1] = p1;
                        ls += p0 + p1;
                    }
                    ls += __shfl_xor_sync(0xffffffffu, ls, 1);
                    ls += __shfl_xor_sync(0xffffffffu, ls, 2);
                    l_p[rs] = ls;
                    if (tig == 0) {
                        float2 w = { rm, ls };
                        ML[wn * 128 + rb + mf * 16 + g + 8 * s] = w;
                    }
                }

            // pair barrier (warps wm and wm+4), then combine with partner stats
            asm volatile("bar.sync %0, %1;" :: "r"(wm + 1), "r"(64) : "memory");

            #pragma unroll
            for (int mf = 0; mf < 2; mf++)
                #pragma unroll
                for (int s = 0; s < 2; s++) {
                    const int rs = mf * 2 + s;
                    const int row = rb + mf * 16 + g + 8 * s;
                    const float2 oth = ML[(1 - wn) * 128 + row];
                    const float m_new = fmaxf(mr[rs], fmaxf(m_p[rs], oth.x));
                    const float alpha  = fast_exp2((mr[rs]  - m_new) * l2s);
                    const float sc_own = fast_exp2((m_p[rs] - m_new) * l2s);
                    const float sc_oth = fast_exp2((oth.x   - m_new) * l2s);
                    lr[rs] = lr[rs] * alpha + l_p[rs] * sc_own + oth.y * sc_oth;
                    mr[rs] = m_new;
                    #pragma unroll
                    for (int nb = 0; nb < 8; nb++) {
                        acc[mf][nb][2*s]   *= alpha;
                        acc[mf][nb][2*s+1] *= alpha;
                    }
                    // P (rescaled to global max) -> smem, warp-private region
                    const int prow = row * 68 + cb;
                    #pragma unroll
                    for (int nb = 0; nb < 4; nb++) {
                        uint2 pv = { f2tf32(sA[mf][nb][2*s]   * sc_own),
                                     f2tf32(sA[mf][nb][2*s+1] * sc_own) };
                        *(uint2*)&Pu[prow + nb * 8 + 2 * tig] = pv;
                    }
                }
            __syncwarp();   // P visible within warp before A-frag reload
        }

        // prefetch next V tile into registers
        #pragma unroll
        for (int r = 0; r < 4; r++)
            rv[r] = *(const float4*)(Vg + (size_t)(knext + sr0 + r * 16) * DKK + c4 * 4);

        if (active) {
            // ---- O += P V over this warp's 32 K-cols: 4 k-steps, 2 mf x 8 nb
            #pragma unroll
            for (int kc = 0; kc < 32; kc += 8) {
                uint32_t a[2][4];
                #pragma unroll
                for (int mf = 0; mf < 2; mf++) {
                    const int ar = (rb + mf * 16 + g) * 68 + cb + kc + tig;
                    a[mf][0] = Pu[ar];
                    a[mf][1] = Pu[ar + 8 * 68];
                    a[mf][2] = Pu[ar + 4];
                    a[mf][3] = Pu[ar + 8 * 68 + 4];
                }
                const int vb0 = (cb + kc + tig) * 72 + g;
                const int vb1 = (cb + kc + tig + 4) * 72 + g;
                #pragma unroll
                for (int nb = 0; nb < 8; nb++) {
                    const uint32_t b0 = Vu[vb0 + nb * 8], b1 = Vu[vb1 + nb * 8];
                    mma_tf32(acc[0][nb][0], acc[0][nb][1], acc[0][nb][2], acc[0][nb][3],
                             a[0][0], a[0][1], a[0][2], a[0][3], b0, b1);
                    mma_tf32(acc[1][nb][0], acc[1][nb][1], acc[1][nb][2], acc[1][nb][3],
                             a[1][0], a[1][1], a[1][2], a[1][3], b0, b1);
                }
            }
        }

        // STS prefetched K/V into the other buffer (ordered by next iter's sync)
        {
            uint32_t* Kw = Kb + ((kt + 1) & 1) * 64 * 68;
            uint32_t* Vw = Vb + ((kt + 1) & 1) * 64 * 72;
            #pragma unroll
            for (int r = 0; r < 4; r++) {
                const int row = sr0 + r * 16;
                uint4 uk = { f2tf32(rk[r].x), f2tf32(rk[r].y), f2tf32(rk[r].z), f2tf32(rk[r].w) };
                uint4 uv = { f2tf32(rv[r].x), f2tf32(rv[r].y), f2tf32(rv[r].z), f2tf32(rv[r].w) };
                *(uint4*)&Kw[row * 68 + c4 * 4] = uk;
                *(uint4*)&Vw[row * 72 + c4 * 4] = uv;
            }
        }
    }

    // ---- pair-reduce the column-split O partials and store
    __syncthreads();   // all PV reads of Pu done
    if (wn == 1) {
        #pragma unroll
        for (int mf = 0; mf < 2; mf++)
            #pragma unroll
            for (int s = 0; s < 2; s++) {
                const int row = rb + mf * 16 + g + 8 * s;
                #pragma unroll
                for (int nb = 0; nb < 8; nb++) {
                    float2 v = { acc[mf][nb][2*s], acc[mf][nb][2*s+1] };
                    *(float2*)&Pf[row * 68 + nb * 8 + 2 * tig] = v;
                }
            }
    }
    __syncthreads();
    if (wn == 0) {
        const int b = bh >> 4, h = bh & 15;
        float* Og = g_o + ((size_t)(b * TT + q0)) * DD + h * DKK;
        #pragma unroll
        for (int mf = 0; mf < 2; mf++)
            #pragma unroll
            for (int s = 0; s < 2; s++) {
                const int rs = mf * 2 + s;
                const int row = rb + mf * 16 + g + 8 * s;
                const float inv = 1.0f / lr[rs];
                float* orow = Og + (size_t)row * DD;
                #pragma unroll
                for (int nb = 0; nb < 8; nb++) {
                    float2 pv = *(float2*)&Pf[row * 68 + nb * 8 + 2 * tig];
                    float2 v = { (acc[mf][nb][2*s]   + pv.x) * inv,
                                 (acc[mf][nb][2*s+1] + pv.y) * inv };
                    *(float2*)(orow + nb * 8 + 2 * tig) = v;
                }
            }
    }
}

// ---------------------------------------------------------------------------
// Kernel 3: output projection y = o @ Wp^T + bp, TF32, double-buffered BK=32.
// (unchanged)
// ---------------------------------------------------------------------------
__global__ __launch_bounds__(256) void proj_kernel(
    const float* __restrict__ Wp, const float* __restrict__ bp,
    float* __restrict__ y)
{
    extern __shared__ float psm[];
    uint32_t* Ob = (uint32_t*)psm;          // [2][128*36]
    uint32_t* Wb = Ob + 2 * 128 * 36;       // [2][128*36]

    const int j0 = blockIdx.x * 128;
    const int r0 = blockIdx.y * 128;
    const int tid = threadIdx.x;
    const int wid = tid >> 5, lane = tid & 31;
    const int g = lane >> 2, tig = lane & 3;
    const int wm = wid & 3, wn = wid >> 2;
    const int c4 = tid & 7, rb = tid >> 3;

    #pragma unroll
    for (int r = 0; r < 4; r++) {
        const int row = rb + 32 * r;
        float4 vo = *(const float4*)(g_o + (size_t)(r0 + row) * DD + c4 * 4);
        float4 vw = *(const float4*)(Wp  + (size_t)(j0 + row) * DD + c4 * 4);
        uint4 uo = { f2tf32(vo.x), f2tf32(vo.y), f2tf32(vo.z), f2tf32(vo.w) };
        uint4 uw = { f2tf32(vw.x), f2tf32(vw.y), f2tf32(vw.z), f2tf32(vw.w) };
        *(uint4*)&Ob[row * 36 + c4 * 4] = uo;
        *(uint4*)&Wb[row * 36 + c4 * 4] = uw;
    }

    float acc[2][8][4];
    #pragma unroll
    for (int mf = 0; mf < 2; mf++)
        #pragma unroll
        for (int nb = 0; nb < 8; nb++)
            #pragma unroll
            for (int c = 0; c < 4; c++) acc[mf][nb][c] = 0.f;

    for (int it = 0; it < 32; it++) {
        const int kcn = min((it + 1) * 32, DD - 32);
        float4 ro[4], rw[4];
        #pragma unroll
        for (int r = 0; r < 4; r++) {
            const int row = rb + 32 * r;
            ro[r] = *(const float4*)(g_o + (size_t)(r0 + row) * DD + kcn + c4 * 4);
            rw[r] = *(const float4*)(Wp  + (size_t)(j0 + row) * DD + kcn + c4 * 4);
        }
        __syncthreads();
        const uint32_t* Ou = Ob + (it & 1) * 128 * 36;
        const uint32_t* Wu = Wb + (it & 1) * 128 * 36;

        #pragma unroll
        for (int k8 = 0; k8 < 4; k8++) {
            const int kk = k8 * 8;
            uint32_t a[2][4];
            #pragma unroll
            for (int mf = 0; mf < 2; mf++) {
                const int ar = (wm * 32 + mf * 16 + g) * 36 + kk + tig;
                a[mf][0] = Ou[ar];
                a[mf][1] = Ou[ar + 8 * 36];
                a[mf][2] = Ou[ar + 4];
                a[mf][3] = Ou[ar + 8 * 36 + 4];
            }
            #pragma unroll
            for (int nb = 0; nb < 8; nb++) {
                const int br = (wn * 64 + nb * 8 + g) * 36 + kk + tig;
                const uint32_t b0 = Wu[br], b1 = Wu[br + 4];
                mma_tf32(acc[0][nb][0], acc[0][nb][1], acc[0][nb][2], acc[0][nb][3],
                         a[0][0], a[0][1], a[0][2], a[0][3], b0, b1);
                mma_tf32(acc[1][nb][0], acc[1][nb][1], acc[1][nb][2], acc[1][nb][3],
                         a[1][0], a[1][1], a[1][2], a[1][3], b0, b1);
            }
        }

        {
            uint32_t* Ow = Ob + ((it + 1) & 1) * 128 * 36;
            uint32_t* Ww = Wb + ((it + 1) & 1) * 128 * 36;
            #pragma unroll
            for (int r = 0; r < 4; r++) {
                const int row = rb + 32 * r;
                uint4 uo = { f2tf32(ro[r].x), f2tf32(ro[r].y), f2tf32(ro[r].z), f2tf32(ro[r].w) };
                uint4 uw = { f2tf32(rw[r].x), f2tf32(rw[r].y), f2tf32(rw[r].z), f2tf32(rw[r].w) };
                *(uint4*)&Ow[row * 36 + c4 * 4] = uo;
                *(uint4*)&Ww[row * 36 + c4 * 4] = uw;
            }
        }
    }

    #pragma unroll
    for (int mf = 0; mf < 2; mf++)
        #pragma unroll
        for (int rs = 0; rs < 2; rs++) {
            const int row = r0 + wm * 32 + mf * 16 + g + 8 * rs;
            float* yr = y + (size_t)row * DD + j0 + wn * 64;
            const float* br = bp + j0 + wn * 64;
            #pragma unroll
            for (int nb = 0; nb < 8; nb++) {
                const int c = nb * 8 + 2 * tig;
                float2 v = { acc[mf][nb][2*rs]   + br[c],
                             acc[mf][nb][2*rs+1] + br[c + 1] };
                *(float2*)(yr + c) = v;
            }
        }
}

// ---------------------------------------------------------------------------
#define QKV_SMEM  ((128*68 + 3*64*68) * (int)sizeof(float))                    // 87,040
#define ATTN_SMEM (((128*68 + 2*64*68 + 2*64*72 + 128*68) * (int)sizeof(float)) + 2*128*8)  // 143,360
#define PROJ_SMEM (4 * 128 * 36 * (int)sizeof(float))                          // 73,728

extern "C" void kernel_launch(void* const* d_in, const int* in_sizes, int n_in,
                              void* d_out, int out_size)
{
    const float* x  = (const float*)d_in[0];
    const float* Wq = (const float*)d_in[1];
    const float* Wk = (const float*)d_in[2];
    const float* Wv = (const float*)d_in[3];
    const float* Wp = (const float*)d_in[4];
    const float* bp = (const float*)d_in[5];
    float* y = (float*)d_out;

    cudaFuncSetAttribute(qkv_kernel,  cudaFuncAttributeMaxDynamicSharedMemorySize, QKV_SMEM);
    cudaFuncSetAttribute(attn_kernel, cudaFuncAttributeMaxDynamicSharedMemorySize, ATTN_SMEM);
    cudaFuncSetAttribute(proj_kernel, cudaFuncAttributeMaxDynamicSharedMemorySize, PROJ_SMEM);

    qkv_kernel<<<dim3(TT / 128, BH), 256, QKV_SMEM>>>(x, Wq, Wk, Wv);
    attn_kernel<<<dim3(TT / 128, BH), 256, ATTN_SMEM>>>();
    proj_kernel<<<dim3(DD / 128, (BB * TT) / 128), 256, PROJ_SMEM>>>(Wp, bp, y);
}